// round 10
// baseline (speedup 1.0000x reference)
#include <cuda_runtime.h>
#include <cuda_bf16.h>
#include <math.h>

// ---------------------------------------------------------------------------
// GCN forward, 5 launches:
//   [prologue persistent kernel: zero, count, scan, dinv, convert, scatter]
//   agg1 (warp/node CSR gather, bf16) -> gemm1 (f32x2 FFMA, bf16 out)
//   agg2+pool (warp/node, smem staging) -> final (W2+MLP+log_softmax)
// ---------------------------------------------------------------------------

#define MAXN 100000
#define MAXE 1600000
#define MAXG 64
#define NBP 148
#define TPB 256

__device__ int   g_indeg[MAXN];
__device__ int   g_rowptr[MAXN + 1];
__device__ int   g_cursor[MAXN];
__device__ int   g_col[MAXE];
__device__ int   g_bsum[NBP];
__device__ int   g_cnti[MAXG];
__device__ float g_dinv[MAXN];
__device__ __align__(16) __nv_bfloat16 g_xb[(size_t)MAXN * 64];
__device__ __align__(16) __nv_bfloat16 g_hb[(size_t)MAXN * 128];
__device__ __align__(16) float g_t1[(size_t)MAXN * 64];
__device__ float g_pooled[MAXG * 128];

// ------------- software grid barrier (sense reversal, persistent grid) -------
__device__ unsigned g_bar_count = 0;
__device__ unsigned g_bar_sense = 0;

__device__ __forceinline__ void grid_barrier() {
    __threadfence();
    __syncthreads();
    if (threadIdx.x == 0) {
        unsigned old = *(volatile unsigned*)&g_bar_sense;
        unsigned ticket = atomicAdd(&g_bar_count, 1u);
        if (ticket == NBP - 1) {
            g_bar_count = 0;
            __threadfence();
            atomicAdd(&g_bar_sense, 1u);
        } else {
            while (*(volatile unsigned*)&g_bar_sense == old) {}
        }
    }
    __syncthreads();
}

// ---------------- prologue: all CSR/dinv/convert phases in one kernel --------
__global__ void __launch_bounds__(TPB) prologue_kernel(const float* __restrict__ x,
                                                       const int* __restrict__ ei,
                                                       const int* __restrict__ batch,
                                                       int n, int e, int G) {
    __shared__ int wsum[8];
    int tid = threadIdx.x;
    int b = blockIdx.x;
    int gid = b * TPB + tid;
    const int gstride = NBP * TPB;

    // Phase A: zero scratch
    for (int i = gid; i < n; i += gstride) g_indeg[i] = 0;
    if (gid < G * 128) g_pooled[gid] = 0.0f;
    if (gid < G) g_cnti[gid] = 0;
    grid_barrier();

    // Phase B: count in-degrees
    for (int idx = gid; idx < e; idx += gstride) atomicAdd(&g_indeg[ei[e + idx]], 1);
    grid_barrier();

    // Phase C: block-local exclusive scan over this block's node chunk
    const int chunk = (n + NBP - 1) / NBP;          // 676 for n=100000
    const int c0 = b * chunk;
    const int c1 = (c0 + chunk < n) ? (c0 + chunk) : n;
    {
        int v0 = 0, v1 = 0, v2 = 0;
        int base = c0 + tid * 3;
        if (base + 0 < c1) v0 = g_indeg[base + 0];
        if (base + 1 < c1) v1 = g_indeg[base + 1];
        if (base + 2 < c1) v2 = g_indeg[base + 2];
        int tsum = v0 + v1 + v2;
        int lane = tid & 31, w = tid >> 5;
        int incl = tsum;
#pragma unroll
        for (int off = 1; off < 32; off <<= 1) {
            int tmp = __shfl_up_sync(0xffffffffu, incl, off);
            if (lane >= off) incl += tmp;
        }
        if (lane == 31) wsum[w] = incl;
        __syncthreads();
        if (tid == 0) {
            int s = 0;
#pragma unroll
            for (int k = 0; k < 8; k++) { int t2 = wsum[k]; wsum[k] = s; s += t2; }
            g_bsum[b] = s;
        }
        __syncthreads();
        int texcl = wsum[w] + incl - tsum;
        if (base + 0 < c1) g_rowptr[base + 0] = texcl;
        if (base + 1 < c1) g_rowptr[base + 1] = texcl + v0;
        if (base + 2 < c1) g_rowptr[base + 2] = texcl + v0 + v1;
    }
    grid_barrier();

    // Phase D: block 0 warp 0 scans the NBP block sums
    if (b == 0 && tid < 32) {
        int lane = tid;
        int carry = 0;
        for (int base = 0; base < NBP; base += 32) {
            int idx = base + lane;
            int v = (idx < NBP) ? g_bsum[idx] : 0;
            int incl = v;
#pragma unroll
            for (int off = 1; off < 32; off <<= 1) {
                int tmp = __shfl_up_sync(0xffffffffu, incl, off);
                if (lane >= off) incl += tmp;
            }
            if (idx < NBP) g_bsum[idx] = carry + incl - v;
            carry += __shfl_sync(0xffffffffu, incl, 31);
        }
        if (lane == 0) g_rowptr[n] = carry;
    }
    grid_barrier();

    // Phase E: finalize chunk (global offset, cursor, dinv, graph counts)
    {
        int off = g_bsum[b];
        for (int i = c0 + tid; i < c1; i += TPB) {
            int r = g_rowptr[i] + off;
            g_rowptr[i] = r;
            g_cursor[i] = r;
            g_dinv[i] = rsqrtf((float)(g_indeg[i] + 1));
            atomicAdd(&g_cnti[batch[i]], 1);
        }
        __syncthreads();   // dinv of this chunk now visible block-locally
        // convert this chunk's x rows: xb' = bf16(dinv * x), float4 granularity
        for (int idx = c0 * 16 + tid; idx < c1 * 16; idx += TPB) {
            float d = g_dinv[idx >> 4];
            float4 v = ((const float4*)x)[idx];
            __nv_bfloat162 lo = __floats2bfloat162_rn(d * v.x, d * v.y);
            __nv_bfloat162 hi = __floats2bfloat162_rn(d * v.z, d * v.w);
            uint2 packed;
            packed.x = *reinterpret_cast<unsigned int*>(&lo);
            packed.y = *reinterpret_cast<unsigned int*>(&hi);
            ((uint2*)g_xb)[idx] = packed;
        }
    }
    grid_barrier();

    // Phase F: scatter edges into CSR
    for (int idx = gid; idx < e; idx += gstride) {
        int s = ei[idx];
        int d = ei[e + idx];
        int pos = atomicAdd(&g_cursor[d], 1);
        g_col[pos] = s;
    }
}

// ---------------- agg1: t1_i = di*(sum xb'_s + xb'_i)  (warp per node) --------
__global__ void agg1_kernel(int n) {
    int warp = (blockIdx.x * blockDim.x + threadIdx.x) >> 5;
    int lane = threadIdx.x & 31;
    if (warp >= n) return;
    int i = warp;
    int p0 = g_rowptr[i], p1 = g_rowptr[i + 1];
    float2 acc = make_float2(0.f, 0.f);
    int p = p0;
    for (; p + 8 <= p1; p += 8) {
        int s0 = g_col[p],     s1 = g_col[p + 1], s2 = g_col[p + 2], s3 = g_col[p + 3];
        int s4 = g_col[p + 4], s5 = g_col[p + 5], s6 = g_col[p + 6], s7 = g_col[p + 7];
        float2 v0 = __bfloat1622float2(*(const __nv_bfloat162*)(g_xb + (size_t)s0 * 64 + lane * 2));
        float2 v1 = __bfloat1622float2(*(const __nv_bfloat162*)(g_xb + (size_t)s1 * 64 + lane * 2));
        float2 v2 = __bfloat1622float2(*(const __nv_bfloat162*)(g_xb + (size_t)s2 * 64 + lane * 2));
        float2 v3 = __bfloat1622float2(*(const __nv_bfloat162*)(g_xb + (size_t)s3 * 64 + lane * 2));
        float2 v4 = __bfloat1622float2(*(const __nv_bfloat162*)(g_xb + (size_t)s4 * 64 + lane * 2));
        float2 v5 = __bfloat1622float2(*(const __nv_bfloat162*)(g_xb + (size_t)s5 * 64 + lane * 2));
        float2 v6 = __bfloat1622float2(*(const __nv_bfloat162*)(g_xb + (size_t)s6 * 64 + lane * 2));
        float2 v7 = __bfloat1622float2(*(const __nv_bfloat162*)(g_xb + (size_t)s7 * 64 + lane * 2));
        acc.x += v0.x + v1.x + v2.x + v3.x + v4.x + v5.x + v6.x + v7.x;
        acc.y += v0.y + v1.y + v2.y + v3.y + v4.y + v5.y + v6.y + v7.y;
    }
    for (; p < p1; ++p) {
        int s = g_col[p];
        float2 v = __bfloat1622float2(*(const __nv_bfloat162*)(g_xb + (size_t)s * 64 + lane * 2));
        acc.x += v.x; acc.y += v.y;
    }
    float di = g_dinv[i];
    float2 xi = __bfloat1622float2(*(const __nv_bfloat162*)(g_xb + (size_t)i * 64 + lane * 2));
    float2 r;
    r.x = di * (acc.x + xi.x);
    r.y = di * (acc.y + xi.y);
    *(float2*)(g_t1 + (size_t)i * 64 + lane * 2) = r;
}

// -------- GEMM1: h = elu(t1 @ W1 + b1); store hb' = bf16(dinv*h) --------------
__global__ void __launch_bounds__(256) gemm1_kernel(const float* __restrict__ W1,
                                                    const float* __restrict__ b1,
                                                    int n) {
    __shared__ float As[64 * 64];
    __shared__ float Ws[64 * 128];
    int tid = threadIdx.x;
    int base = blockIdx.x * 64;

    const float4* Wv = (const float4*)W1;
    float4* Wsv = (float4*)Ws;
#pragma unroll
    for (int i = 0; i < 8; i++) Wsv[tid + i * 256] = Wv[tid + i * 256];

    const float4* Av = (const float4*)(g_t1 + (size_t)base * 64);
    float4* Asv = (float4*)As;
#pragma unroll
    for (int i = 0; i < 4; i++) {
        int idx = tid + i * 256;
        int row = base + (idx >> 4);
        float4 v = (row < n) ? Av[idx] : make_float4(0.f, 0.f, 0.f, 0.f);
        Asv[idx] = v;
    }
    __syncthreads();

    int tx = tid & 31, ty = tid >> 5;
    int c0 = tx * 4, r0 = ty * 8;
    unsigned long long accp[8][2];
#pragma unroll
    for (int r = 0; r < 8; r++) { accp[r][0] = 0ull; accp[r][1] = 0ull; }

#pragma unroll 4
    for (int k = 0; k < 64; k++) {
        ulonglong2 bb = *(const ulonglong2*)(Ws + k * 128 + c0);
#pragma unroll
        for (int r = 0; r < 8; r++) {
            unsigned int au = __float_as_uint(As[(r0 + r) * 64 + k]);
            unsigned long long ap;
            asm("mov.b64 %0, {%1, %1};" : "=l"(ap) : "r"(au));
            asm("fma.rn.f32x2 %0, %1, %2, %0;" : "+l"(accp[r][0]) : "l"(ap), "l"(bb.x));
            asm("fma.rn.f32x2 %0, %1, %2, %0;" : "+l"(accp[r][1]) : "l"(ap), "l"(bb.y));
        }
    }

    float4 bias = *(const float4*)&b1[c0];
#pragma unroll
    for (int r = 0; r < 8; r++) {
        int row = base + r0 + r;
        if (row < n) {
            float di = g_dinv[row];
            unsigned int u0, u1, u2, u3;
            asm("mov.b64 {%0, %1}, %2;" : "=r"(u0), "=r"(u1) : "l"(accp[r][0]));
            asm("mov.b64 {%0, %1}, %2;" : "=r"(u2), "=r"(u3) : "l"(accp[r][1]));
            float4 o;
            o.x = __uint_as_float(u0) + bias.x;
            o.y = __uint_as_float(u1) + bias.y;
            o.z = __uint_as_float(u2) + bias.z;
            o.w = __uint_as_float(u3) + bias.w;
            o.x = (o.x > 0.f) ? o.x : expm1f(o.x);
            o.y = (o.y > 0.f) ? o.y : expm1f(o.y);
            o.z = (o.z > 0.f) ? o.z : expm1f(o.z);
            o.w = (o.w > 0.f) ? o.w : expm1f(o.w);
            __nv_bfloat162 lo = __floats2bfloat162_rn(di * o.x, di * o.y);
            __nv_bfloat162 hi = __floats2bfloat162_rn(di * o.z, di * o.w);
            uint2 packed;
            packed.x = *reinterpret_cast<unsigned int*>(&lo);
            packed.y = *reinterpret_cast<unsigned int*>(&hi);
            *(uint2*)(g_hb + (size_t)row * 128 + c0) = packed;
        }
    }
}

// -------- agg2 + mean-pool: pooled[g] += di*(sum hb'_s + hb'_i) ---------------
__device__ __forceinline__ float4 ld_h4(const __nv_bfloat16* p) {
    uint2 raw = *(const uint2*)p;
    __nv_bfloat162 b0 = *reinterpret_cast<__nv_bfloat162*>(&raw.x);
    __nv_bfloat162 b1 = *reinterpret_cast<__nv_bfloat162*>(&raw.y);
    float2 f0 = __bfloat1622float2(b0);
    float2 f1 = __bfloat1622float2(b1);
    return make_float4(f0.x, f0.y, f1.x, f1.y);
}

__global__ void __launch_bounds__(256) agg2_pool_kernel(const int* __restrict__ batch, int n) {
    __shared__ float ps[128];
    __shared__ int g0_s;
    int tid = threadIdx.x;
    int lane = tid & 31;
    int wid = tid >> 5;
    int node0 = blockIdx.x * 8;
    if (tid < 128) ps[tid] = 0.0f;
    if (tid == 0) g0_s = batch[node0 < n ? node0 : (n - 1)];
    __syncthreads();
    int g0 = g0_s;

    int i = node0 + wid;
    if (i < n) {
        int p0 = g_rowptr[i], p1 = g_rowptr[i + 1];
        float4 acc = make_float4(0.f, 0.f, 0.f, 0.f);
        int p = p0;
        for (; p + 8 <= p1; p += 8) {
            int s0 = g_col[p],     s1 = g_col[p + 1], s2 = g_col[p + 2], s3 = g_col[p + 3];
            int s4 = g_col[p + 4], s5 = g_col[p + 5], s6 = g_col[p + 6], s7 = g_col[p + 7];
            float4 v0 = ld_h4(g_hb + (size_t)s0 * 128 + lane * 4);
            float4 v1 = ld_h4(g_hb + (size_t)s1 * 128 + lane * 4);
            float4 v2 = ld_h4(g_hb + (size_t)s2 * 128 + lane * 4);
            float4 v3 = ld_h4(g_hb + (size_t)s3 * 128 + lane * 4);
            float4 v4 = ld_h4(g_hb + (size_t)s4 * 128 + lane * 4);
            float4 v5 = ld_h4(g_hb + (size_t)s5 * 128 + lane * 4);
            float4 v6 = ld_h4(g_hb + (size_t)s6 * 128 + lane * 4);
            float4 v7 = ld_h4(g_hb + (size_t)s7 * 128 + lane * 4);
            acc.x += v0.x + v1.x + v2.x + v3.x + v4.x + v5.x + v6.x + v7.x;
            acc.y += v0.y + v1.y + v2.y + v3.y + v4.y + v5.y + v6.y + v7.y;
            acc.z += v0.z + v1.z + v2.z + v3.z + v4.z + v5.z + v6.z + v7.z;
            acc.w += v0.w + v1.w + v2.w + v3.w + v4.w + v5.w + v6.w + v7.w;
        }
        for (; p < p1; ++p) {
            int s = g_col[p];
            float4 v = ld_h4(g_hb + (size_t)s * 128 + lane * 4);
            acc.x += v.x; acc.y += v.y; acc.z += v.z; acc.w += v.w;
        }
        float di = g_dinv[i];
        float4 hi = ld_h4(g_hb + (size_t)i * 128 + lane * 4);
        float4 r;
        r.x = di * (acc.x + hi.x);
        r.y = di * (acc.y + hi.y);
        r.z = di * (acc.z + hi.z);
        r.w = di * (acc.w + hi.w);
        int g = batch[i];
        if (g == g0) {
            atomicAdd(&ps[lane * 4 + 0], r.x);
            atomicAdd(&ps[lane * 4 + 1], r.y);
            atomicAdd(&ps[lane * 4 + 2], r.z);
            atomicAdd(&ps[lane * 4 + 3], r.w);
        } else {
            float* pg = g_pooled + g * 128 + lane * 4;
            atomicAdd(pg + 0, r.x);
            atomicAdd(pg + 1, r.y);
            atomicAdd(pg + 2, r.z);
            atomicAdd(pg + 3, r.w);
        }
    }
    __syncthreads();
    if (tid < 128) atomicAdd(&g_pooled[g0 * 128 + tid], ps[tid]);
}

// ---------------- epilogue: W2 + MLP + log_softmax (1 block per graph) --------
__global__ void __launch_bounds__(128) final_kernel(
    const float* __restrict__ stats,
    const float* __restrict__ W2, const float* __restrict__ b2,
    const float* __restrict__ Wf1, const float* __restrict__ bf1,
    const float* __restrict__ Wf2, const float* __restrict__ bf2,
    float* __restrict__ out) {
    __shared__ float pm[128];
    __shared__ float zin[138];
    __shared__ float z1[20];
    __shared__ float z2[5];
    int g = blockIdx.x, t = threadIdx.x;
    float c = fmaxf((float)g_cnti[g], 1.0f);
    pm[t] = g_pooled[g * 128 + t] / c;
    __syncthreads();
    float acc = b2[t];
#pragma unroll 8
    for (int k = 0; k < 128; k++) acc = fmaf(pm[k], W2[k * 128 + t], acc);
    zin[t] = acc;
    if (t < 10) zin[128 + t] = stats[g * 10 + t];
    __syncthreads();
    if (t < 20) {
        float a = bf1[t];
        for (int k = 0; k < 138; k++) a = fmaf(zin[k], Wf1[k * 20 + t], a);
        z1[t] = fmaxf(a, 0.0f);
    }
    __syncthreads();
    if (t < 5) {
        float a = bf2[t];
        for (int k = 0; k < 20; k++) a = fmaf(z1[k], Wf2[k * 5 + t], a);
        z2[t] = a;
    }
    __syncthreads();
    if (t == 0) {
        float m = z2[0];
        for (int i = 1; i < 5; i++) m = fmaxf(m, z2[i]);
        float sum = 0.0f;
        for (int i = 0; i < 5; i++) sum += expf(z2[i] - m);
        float ls = m + logf(sum);
        for (int i = 0; i < 5; i++) out[g * 5 + i] = z2[i] - ls;
    }
}

// ---------------------------------------------------------------------------
extern "C" void kernel_launch(void* const* d_in, const int* in_sizes, int n_in,
                              void* d_out, int out_size) {
    const float* x     = (const float*)d_in[0];
    const int*   ei    = (const int*)d_in[1];
    const int*   batch = (const int*)d_in[2];
    const float* stats = (const float*)d_in[4];
    const float* W1    = (const float*)d_in[5];
    const float* b1    = (const float*)d_in[6];
    const float* W2    = (const float*)d_in[7];
    const float* b2    = (const float*)d_in[8];
    const float* Wf1   = (const float*)d_in[9];
    const float* bf1   = (const float*)d_in[10];
    const float* Wf2   = (const float*)d_in[11];
    const float* bf2   = (const float*)d_in[12];

    int n = in_sizes[0] / 64;
    int e = in_sizes[1] / 2;
    int G = in_sizes[4] / 10;

    prologue_kernel<<<NBP, TPB>>>(x, ei, batch, n, e, G);
    agg1_kernel<<<(n * 32 + 255) / 256, 256>>>(n);
    gemm1_kernel<<<(n + 63) / 64, 256>>>(W1, b1, n);
    agg2_pool_kernel<<<(n + 7) / 8, 256>>>(batch, n);
    final_kernel<<<G, 128>>>(stats, W2, b2, Wf1, bf1, Wf2, bf2, (float*)d_out);
}

// round 11
// speedup vs baseline: 1.0044x; 1.0044x over previous
#include <cuda_runtime.h>
#include <cuda_bf16.h>
#include <math.h>

// ---------------------------------------------------------------------------
// GCN forward, 7 launches:
//   init (zero) -> count (degrees) -> csr (persistent: scan+dinv+convert+scatter)
//   -> agg1 -> gemm1 -> agg2+pool -> final
// bf16 dinv-prescaled payloads; fp32 accumulation everywhere.
// ---------------------------------------------------------------------------

#define MAXN 100000
#define MAXE 1600000
#define MAXG 64
#define NBP 148
#define TPB 256

__device__ int   g_indeg[MAXN];
__device__ int   g_rowptr[MAXN + 1];
__device__ int   g_cursor[MAXN];
__device__ int   g_col[MAXE];
__device__ int   g_bsum[NBP];
__device__ int   g_cnti[MAXG];
__device__ float g_dinv[MAXN];
__device__ __align__(16) __nv_bfloat16 g_xb[(size_t)MAXN * 64];
__device__ __align__(16) __nv_bfloat16 g_hb[(size_t)MAXN * 128];
__device__ __align__(16) float g_t1[(size_t)MAXN * 64];
__device__ float g_pooled[MAXG * 128];

// ------------- software grid barrier (sense reversal, persistent grid) -------
__device__ unsigned g_bar_count = 0;
__device__ unsigned g_bar_sense = 0;

__device__ __forceinline__ void grid_barrier() {
    __threadfence();
    __syncthreads();
    if (threadIdx.x == 0) {
        unsigned old = *(volatile unsigned*)&g_bar_sense;
        unsigned ticket = atomicAdd(&g_bar_count, 1u);
        if (ticket == NBP - 1) {
            g_bar_count = 0;
            __threadfence();
            atomicAdd(&g_bar_sense, 1u);
        } else {
            while (*(volatile unsigned*)&g_bar_sense == old) {}
        }
    }
    __syncthreads();
}

// ---------------- init: zero scratch -----------------------------------------
__global__ void init_kernel(int n, int G) {
    int i = blockIdx.x * blockDim.x + threadIdx.x;
    if (i < n) g_indeg[i] = 0;
    if (i < G * 128) g_pooled[i] = 0.0f;
    if (i < G) g_cnti[i] = 0;
}

// ---------------- count in-degrees -------------------------------------------
__global__ void count_kernel(const int* __restrict__ ei, int e) {
    int idx = blockIdx.x * blockDim.x + threadIdx.x;
    if (idx < e) atomicAdd(&g_indeg[ei[e + idx]], 1);
}

// ------- csr: scan + dinv + cursor + graph counts + convert + scatter --------
__global__ void __launch_bounds__(TPB) csr_kernel(const float* __restrict__ x,
                                                  const int* __restrict__ ei,
                                                  const int* __restrict__ batch,
                                                  int n, int e) {
    __shared__ int wsum[8];
    int tid = threadIdx.x;
    int b = blockIdx.x;
    const int gstride = NBP * TPB;

    // Phase C: block-local exclusive scan over this block's node chunk
    const int chunk = (n + NBP - 1) / NBP;
    const int c0 = b * chunk;
    const int c1 = (c0 + chunk < n) ? (c0 + chunk) : n;
    {
        int v0 = 0, v1 = 0, v2 = 0;
        int base = c0 + tid * 3;
        if (base + 0 < c1) v0 = g_indeg[base + 0];
        if (base + 1 < c1) v1 = g_indeg[base + 1];
        if (base + 2 < c1) v2 = g_indeg[base + 2];
        int tsum = v0 + v1 + v2;
        int lane = tid & 31, w = tid >> 5;
        int incl = tsum;
#pragma unroll
        for (int off = 1; off < 32; off <<= 1) {
            int tmp = __shfl_up_sync(0xffffffffu, incl, off);
            if (lane >= off) incl += tmp;
        }
        if (lane == 31) wsum[w] = incl;
        __syncthreads();
        if (tid == 0) {
            int s = 0;
#pragma unroll
            for (int k = 0; k < 8; k++) { int t2 = wsum[k]; wsum[k] = s; s += t2; }
            g_bsum[b] = s;
        }
        __syncthreads();
        int texcl = wsum[w] + incl - tsum;
        if (base + 0 < c1) g_rowptr[base + 0] = texcl;
        if (base + 1 < c1) g_rowptr[base + 1] = texcl + v0;
        if (base + 2 < c1) g_rowptr[base + 2] = texcl + v0 + v1;
    }
    grid_barrier();

    // Phase D: block 0 warp 0 scans the NBP block sums
    if (b == 0 && tid < 32) {
        int lane = tid;
        int carry = 0;
        for (int base = 0; base < NBP; base += 32) {
            int idx = base + lane;
            int v = (idx < NBP) ? g_bsum[idx] : 0;
            int incl = v;
#pragma unroll
            for (int off = 1; off < 32; off <<= 1) {
                int tmp = __shfl_up_sync(0xffffffffu, incl, off);
                if (lane >= off) incl += tmp;
            }
            if (idx < NBP) g_bsum[idx] = carry + incl - v;
            carry += __shfl_sync(0xffffffffu, incl, 31);
        }
        if (lane == 0) g_rowptr[n] = carry;
    }
    grid_barrier();

    // Phase E: finalize chunk (offsets, cursor, dinv, counts) + convert x chunk
    {
        int off = g_bsum[b];
        for (int i = c0 + tid; i < c1; i += TPB) {
            int r = g_rowptr[i] + off;
            g_rowptr[i] = r;
            g_cursor[i] = r;
            g_dinv[i] = rsqrtf((float)(g_indeg[i] + 1));
            atomicAdd(&g_cnti[batch[i]], 1);
        }
        __syncthreads();
        for (int idx = c0 * 16 + tid; idx < c1 * 16; idx += TPB) {
            float d = g_dinv[idx >> 4];
            float4 v = ((const float4*)x)[idx];
            __nv_bfloat162 lo = __floats2bfloat162_rn(d * v.x, d * v.y);
            __nv_bfloat162 hi = __floats2bfloat162_rn(d * v.z, d * v.w);
            uint2 packed;
            packed.x = *reinterpret_cast<unsigned int*>(&lo);
            packed.y = *reinterpret_cast<unsigned int*>(&hi);
            ((uint2*)g_xb)[idx] = packed;
        }
    }
    grid_barrier();

    // Phase F: scatter edges into CSR (full-grid stride)
    for (int idx = b * TPB + tid; idx < e; idx += gstride) {
        int s = ei[idx];
        int d = ei[e + idx];
        int pos = atomicAdd(&g_cursor[d], 1);
        g_col[pos] = s;
    }
}

// ---------------- agg1: t1_i = di*(sum xb'_s + xb'_i)  (warp per node) --------
__global__ void agg1_kernel(int n) {
    int warp = (blockIdx.x * blockDim.x + threadIdx.x) >> 5;
    int lane = threadIdx.x & 31;
    if (warp >= n) return;
    int i = warp;
    const char* xb = (const char*)g_xb + lane * 4;
    int p0 = g_rowptr[i], p1 = g_rowptr[i + 1];
    float2 acc = make_float2(0.f, 0.f);
    int p = p0;
    for (; p + 8 <= p1; p += 8) {
        unsigned o0 = (unsigned)g_col[p]     << 7, o1 = (unsigned)g_col[p + 1] << 7;
        unsigned o2 = (unsigned)g_col[p + 2] << 7, o3 = (unsigned)g_col[p + 3] << 7;
        unsigned o4 = (unsigned)g_col[p + 4] << 7, o5 = (unsigned)g_col[p + 5] << 7;
        unsigned o6 = (unsigned)g_col[p + 6] << 7, o7 = (unsigned)g_col[p + 7] << 7;
        float2 v0 = __bfloat1622float2(*(const __nv_bfloat162*)(xb + o0));
        float2 v1 = __bfloat1622float2(*(const __nv_bfloat162*)(xb + o1));
        float2 v2 = __bfloat1622float2(*(const __nv_bfloat162*)(xb + o2));
        float2 v3 = __bfloat1622float2(*(const __nv_bfloat162*)(xb + o3));
        float2 v4 = __bfloat1622float2(*(const __nv_bfloat162*)(xb + o4));
        float2 v5 = __bfloat1622float2(*(const __nv_bfloat162*)(xb + o5));
        float2 v6 = __bfloat1622float2(*(const __nv_bfloat162*)(xb + o6));
        float2 v7 = __bfloat1622float2(*(const __nv_bfloat162*)(xb + o7));
        acc.x += v0.x + v1.x + v2.x + v3.x + v4.x + v5.x + v6.x + v7.x;
        acc.y += v0.y + v1.y + v2.y + v3.y + v4.y + v5.y + v6.y + v7.y;
    }
    for (; p < p1; ++p) {
        unsigned o = (unsigned)g_col[p] << 7;
        float2 v = __bfloat1622float2(*(const __nv_bfloat162*)(xb + o));
        acc.x += v.x; acc.y += v.y;
    }
    float di = g_dinv[i];
    float2 xi = __bfloat1622float2(*(const __nv_bfloat162*)(xb + ((unsigned)i << 7)));
    float2 r;
    r.x = di * (acc.x + xi.x);
    r.y = di * (acc.y + xi.y);
    *(float2*)(g_t1 + (size_t)i * 64 + lane * 2) = r;
}

// -------- GEMM1: h = elu(t1 @ W1 + b1); store hb' = bf16(dinv*h) --------------
__global__ void __launch_bounds__(256) gemm1_kernel(const float* __restrict__ W1,
                                                    const float* __restrict__ b1,
                                                    int n) {
    __shared__ float As[64 * 64];
    __shared__ float Ws[64 * 128];
    int tid = threadIdx.x;
    int base = blockIdx.x * 64;

    const float4* Wv = (const float4*)W1;
    float4* Wsv = (float4*)Ws;
#pragma unroll
    for (int i = 0; i < 8; i++) Wsv[tid + i * 256] = Wv[tid + i * 256];

    const float4* Av = (const float4*)(g_t1 + (size_t)base * 64);
    float4* Asv = (float4*)As;
#pragma unroll
    for (int i = 0; i < 4; i++) {
        int idx = tid + i * 256;
        int row = base + (idx >> 4);
        float4 v = (row < n) ? Av[idx] : make_float4(0.f, 0.f, 0.f, 0.f);
        Asv[idx] = v;
    }
    __syncthreads();

    int tx = tid & 31, ty = tid >> 5;
    int c0 = tx * 4, r0 = ty * 8;
    unsigned long long accp[8][2];
#pragma unroll
    for (int r = 0; r < 8; r++) { accp[r][0] = 0ull; accp[r][1] = 0ull; }

#pragma unroll 4
    for (int k = 0; k < 64; k++) {
        ulonglong2 bb = *(const ulonglong2*)(Ws + k * 128 + c0);
#pragma unroll
        for (int r = 0; r < 8; r++) {
            unsigned int au = __float_as_uint(As[(r0 + r) * 64 + k]);
            unsigned long long ap;
            asm("mov.b64 %0, {%1, %1};" : "=l"(ap) : "r"(au));
            asm("fma.rn.f32x2 %0, %1, %2, %0;" : "+l"(accp[r][0]) : "l"(ap), "l"(bb.x));
            asm("fma.rn.f32x2 %0, %1, %2, %0;" : "+l"(accp[r][1]) : "l"(ap), "l"(bb.y));
        }
    }

    float4 bias = *(const float4*)&b1[c0];
#pragma unroll
    for (int r = 0; r < 8; r++) {
        int row = base + r0 + r;
        if (row < n) {
            float di = g_dinv[row];
            unsigned int u0, u1, u2, u3;
            asm("mov.b64 {%0, %1}, %2;" : "=r"(u0), "=r"(u1) : "l"(accp[r][0]));
            asm("mov.b64 {%0, %1}, %2;" : "=r"(u2), "=r"(u3) : "l"(accp[r][1]));
            float4 o;
            o.x = __uint_as_float(u0) + bias.x;
            o.y = __uint_as_float(u1) + bias.y;
            o.z = __uint_as_float(u2) + bias.z;
            o.w = __uint_as_float(u3) + bias.w;
            o.x = (o.x > 0.f) ? o.x : expm1f(o.x);
            o.y = (o.y > 0.f) ? o.y : expm1f(o.y);
            o.z = (o.z > 0.f) ? o.z : expm1f(o.z);
            o.w = (o.w > 0.f) ? o.w : expm1f(o.w);
            __nv_bfloat162 lo = __floats2bfloat162_rn(di * o.x, di * o.y);
            __nv_bfloat162 hi = __floats2bfloat162_rn(di * o.z, di * o.w);
            uint2 packed;
            packed.x = *reinterpret_cast<unsigned int*>(&lo);
            packed.y = *reinterpret_cast<unsigned int*>(&hi);
            *(uint2*)(g_hb + (size_t)row * 128 + c0) = packed;
        }
    }
}

// -------- agg2 + mean-pool: pooled[g] += di*(sum hb'_s + hb'_i) ---------------
__device__ __forceinline__ float4 ld_h4o(const char* base, unsigned off) {
    uint2 raw = *(const uint2*)(base + off);
    __nv_bfloat162 b0 = *reinterpret_cast<__nv_bfloat162*>(&raw.x);
    __nv_bfloat162 b1 = *reinterpret_cast<__nv_bfloat162*>(&raw.y);
    float2 f0 = __bfloat1622float2(b0);
    float2 f1 = __bfloat1622float2(b1);
    return make_float4(f0.x, f0.y, f1.x, f1.y);
}

__global__ void __launch_bounds__(256) agg2_pool_kernel(const int* __restrict__ batch, int n) {
    __shared__ float ps[128];
    __shared__ int g0_s;
    int tid = threadIdx.x;
    int lane = tid & 31;
    int wid = tid >> 5;
    int node0 = blockIdx.x * 8;
    if (tid < 128) ps[tid] = 0.0f;
    if (tid == 0) g0_s = batch[node0 < n ? node0 : (n - 1)];
    __syncthreads();
    int g0 = g0_s;

    int i = node0 + wid;
    if (i < n) {
        const char* hb = (const char*)g_hb + lane * 8;
        int p0 = g_rowptr[i], p1 = g_rowptr[i + 1];
        float4 acc = make_float4(0.f, 0.f, 0.f, 0.f);
        int p = p0;
        for (; p + 8 <= p1; p += 8) {
            unsigned o0 = (unsigned)g_col[p]     << 8, o1 = (unsigned)g_col[p + 1] << 8;
            unsigned o2 = (unsigned)g_col[p + 2] << 8, o3 = (unsigned)g_col[p + 3] << 8;
            unsigned o4 = (unsigned)g_col[p + 4] << 8, o5 = (unsigned)g_col[p + 5] << 8;
            unsigned o6 = (unsigned)g_col[p + 6] << 8, o7 = (unsigned)g_col[p + 7] << 8;
            float4 v0 = ld_h4o(hb, o0);
            float4 v1 = ld_h4o(hb, o1);
            float4 v2 = ld_h4o(hb, o2);
            float4 v3 = ld_h4o(hb, o3);
            float4 v4 = ld_h4o(hb, o4);
            float4 v5 = ld_h4o(hb, o5);
            float4 v6 = ld_h4o(hb, o6);
            float4 v7 = ld_h4o(hb, o7);
            acc.x += v0.x + v1.x + v2.x + v3.x + v4.x + v5.x + v6.x + v7.x;
            acc.y += v0.y + v1.y + v2.y + v3.y + v4.y + v5.y + v6.y + v7.y;
            acc.z += v0.z + v1.z + v2.z + v3.z + v4.z + v5.z + v6.z + v7.z;
            acc.w += v0.w + v1.w + v2.w + v3.w + v4.w + v5.w + v6.w + v7.w;
        }
        for (; p < p1; ++p) {
            float4 v = ld_h4o(hb, (unsigned)g_col[p] << 8);
            acc.x += v.x; acc.y += v.y; acc.z += v.z; acc.w += v.w;
        }
        float di = g_dinv[i];
        float4 hi = ld_h4o(hb, (unsigned)i << 8);
        float4 r;
        r.x = di * (acc.x + hi.x);
        r.y = di * (acc.y + hi.y);
        r.z = di * (acc.z + hi.z);
        r.w = di * (acc.w + hi.w);
        int g = batch[i];
        if (g == g0) {
            atomicAdd(&ps[lane * 4 + 0], r.x);
            atomicAdd(&ps[lane * 4 + 1], r.y);
            atomicAdd(&ps[lane * 4 + 2], r.z);
            atomicAdd(&ps[lane * 4 + 3], r.w);
        } else {
            float* pg = g_pooled + g * 128 + lane * 4;
            atomicAdd(pg + 0, r.x);
            atomicAdd(pg + 1, r.y);
            atomicAdd(pg + 2, r.z);
            atomicAdd(pg + 3, r.w);
        }
    }
    __syncthreads();
    if (tid < 128) atomicAdd(&g_pooled[g0 * 128 + tid], ps[tid]);
}

// ---------------- epilogue: W2 + MLP + log_softmax (1 block per graph) --------
__global__ void __launch_bounds__(128) final_kernel(
    const float* __restrict__ stats,
    const float* __restrict__ W2, const float* __restrict__ b2,
    const float* __restrict__ Wf1, const float* __restrict__ bf1,
    const float* __restrict__ Wf2, const float* __restrict__ bf2,
    float* __restrict__ out) {
    __shared__ float pm[128];
    __shared__ float zin[138];
    __shared__ float z1[20];
    __shared__ float z2[5];
    int g = blockIdx.x, t = threadIdx.x;
    float c = fmaxf((float)g_cnti[g], 1.0f);
    pm[t] = g_pooled[g * 128 + t] / c;
    __syncthreads();
    float acc = b2[t];
#pragma unroll 8
    for (int k = 0; k < 128; k++) acc = fmaf(pm[k], W2[k * 128 + t], acc);
    zin[t] = acc;
    if (t < 10) zin[128 + t] = stats[g * 10 + t];
    __syncthreads();
    if (t < 20) {
        float a = bf1[t];
        for (int k = 0; k < 138; k++) a = fmaf(zin[k], Wf1[k * 20 + t], a);
        z1[t] = fmaxf(a, 0.0f);
    }
    __syncthreads();
    if (t < 5) {
        float a = bf2[t];
        for (int k = 0; k < 20; k++) a = fmaf(z1[k], Wf2[k * 5 + t], a);
        z2[t] = a;
    }
    __syncthreads();
    if (t == 0) {
        float m = z2[0];
        for (int i = 1; i < 5; i++) m = fmaxf(m, z2[i]);
        float sum = 0.0f;
        for (int i = 0; i < 5; i++) sum += expf(z2[i] - m);
        float ls = m + logf(sum);
        for (int i = 0; i < 5; i++) out[g * 5 + i] = z2[i] - ls;
    }
}

// ---------------------------------------------------------------------------
extern "C" void kernel_launch(void* const* d_in, const int* in_sizes, int n_in,
                              void* d_out, int out_size) {
    const float* x     = (const float*)d_in[0];
    const int*   ei    = (const int*)d_in[1];
    const int*   batch = (const int*)d_in[2];
    const float* stats = (const float*)d_in[4];
    const float* W1    = (const float*)d_in[5];
    const float* b1    = (const float*)d_in[6];
    const float* W2    = (const float*)d_in[7];
    const float* b2    = (const float*)d_in[8];
    const float* Wf1   = (const float*)d_in[9];
    const float* bf1   = (const float*)d_in[10];
    const float* Wf2   = (const float*)d_in[11];
    const float* bf2   = (const float*)d_in[12];

    int n = in_sizes[0] / 64;
    int e = in_sizes[1] / 2;
    int G = in_sizes[4] / 10;

    init_kernel<<<(n + 255) / 256, 256>>>(n, G);
    count_kernel<<<(e + 255) / 256, 256>>>(ei, e);
    csr_kernel<<<NBP, TPB>>>(x, ei, batch, n, e);
    agg1_kernel<<<(n * 32 + 255) / 256, 256>>>(n);
    gemm1_kernel<<<(n + 63) / 64, 256>>>(W1, b1, n);
    agg2_pool_kernel<<<(n + 7) / 8, 256>>>(batch, n);
    final_kernel<<<G, 128>>>(stats, W2, b2, Wf1, bf1, Wf2, bf2, (float*)d_out);
}

// round 12
// speedup vs baseline: 1.0907x; 1.0859x over previous
#include <cuda_runtime.h>
#include <cuda_bf16.h>
#include <math.h>

// ---------------------------------------------------------------------------
// GCN forward (R7 launch structure + shfl-distributed CSR cols):
//   init -> count -> scan1/scan2/scan3 -> convscatter -> agg1 -> gemm1
//   -> agg2+pool -> final
// bf16 dinv-prescaled payloads; fp32 accumulation.
// ---------------------------------------------------------------------------

#define MAXN 100000
#define MAXE 1600000
#define MAXG 64
#define MAXB ((MAXN + 4095) / 4096)

__device__ int   g_indeg[MAXN];
__device__ int   g_rowptr[MAXN + 1];
__device__ int   g_cursor[MAXN];
__device__ int   g_col[MAXE];
__device__ int   g_bsum[MAXB + 1];
__device__ int   g_cnti[MAXG];
__device__ float g_dinv[MAXN];
__device__ __align__(16) __nv_bfloat16 g_xb[(size_t)MAXN * 64];
__device__ __align__(16) __nv_bfloat16 g_hb[(size_t)MAXN * 128];
__device__ __align__(16) float g_t1[(size_t)MAXN * 64];
__device__ float g_pooled[MAXG * 128];

// ---------------- init ---------------------------------------------------------
__global__ void init_kernel(int n, int g) {
    int i = blockIdx.x * blockDim.x + threadIdx.x;
    if (i < n) g_indeg[i] = 0;
    if (i < g * 128) g_pooled[i] = 0.0f;
    if (i < g) g_cnti[i] = 0;
}

// ---------------- count in-degree ----------------------------------------------
__global__ void count_kernel(const int* __restrict__ ei, int e) {
    int idx = blockIdx.x * blockDim.x + threadIdx.x;
    if (idx < e) atomicAdd(&g_indeg[ei[e + idx]], 1);
}

// ---------------- scan phase 1 -------------------------------------------------
__global__ void __launch_bounds__(256) scan1_kernel(int n) {
    __shared__ int sh[4096];
    __shared__ int wsum[8];
    int t = threadIdx.x;
    int base = blockIdx.x * 4096;
#pragma unroll
    for (int j = 0; j < 16; j++) {
        int idx = base + t + j * 256;
        sh[t + j * 256] = (idx < n) ? g_indeg[idx] : 0;
    }
    __syncthreads();
    int v[16];
    int run = 0;
#pragma unroll
    for (int j = 0; j < 16; j++) { v[j] = run; run += sh[t * 16 + j]; }
    int lane = t & 31, w = t >> 5;
    int incl = run;
#pragma unroll
    for (int off = 1; off < 32; off <<= 1) {
        int tmp = __shfl_up_sync(0xffffffffu, incl, off);
        if (lane >= off) incl += tmp;
    }
    if (lane == 31) wsum[w] = incl;
    __syncthreads();
    if (t == 0) {
        int s = 0;
#pragma unroll
        for (int k = 0; k < 8; k++) { int x2 = wsum[k]; wsum[k] = s; s += x2; }
        g_bsum[blockIdx.x] = s;
    }
    __syncthreads();
    int texcl = wsum[w] + incl - run;
#pragma unroll
    for (int j = 0; j < 16; j++) sh[t * 16 + j] = texcl + v[j];
    __syncthreads();
#pragma unroll
    for (int j = 0; j < 16; j++) {
        int idx = base + t + j * 256;
        if (idx < n) g_rowptr[idx] = sh[t + j * 256];
    }
}

// ---------------- scan phase 2 -------------------------------------------------
__global__ void scan2_kernel(int nb, int n) {
    int lane = threadIdx.x;
    int carry = 0;
    for (int base = 0; base < nb; base += 32) {
        int idx = base + lane;
        int x = (idx < nb) ? g_bsum[idx] : 0;
        int incl = x;
#pragma unroll
        for (int off = 1; off < 32; off <<= 1) {
            int tmp = __shfl_up_sync(0xffffffffu, incl, off);
            if (lane >= off) incl += tmp;
        }
        int excl = carry + incl - x;
        if (idx < nb) g_bsum[idx] = excl;
        carry += __shfl_sync(0xffffffffu, incl, 31);
    }
    if (lane == 0) g_rowptr[n] = carry;
}

// -------- scan phase 3: offsets + dinv + cursor + graph counts -----------------
__global__ void scan3_kernel(const int* __restrict__ batch, int n) {
    int i = blockIdx.x * blockDim.x + threadIdx.x;
    if (i < n) {
        int r = g_rowptr[i] + g_bsum[i >> 12];
        g_rowptr[i] = r;
        g_cursor[i] = r;
        g_dinv[i] = rsqrtf((float)(g_indeg[i] + 1));
        atomicAdd(&g_cnti[batch[i]], 1);
    }
}

// -------- convert xb' = bf16(dinv*x) + scatter edges (merged) ------------------
__global__ void convscatter_kernel(const float* __restrict__ x,
                                   const int* __restrict__ ei,
                                   int nconv, int e) {
    int idx = blockIdx.x * blockDim.x + threadIdx.x;
    if (idx < nconv) {
        float d = g_dinv[idx >> 4];
        float4 v = ((const float4*)x)[idx];
        __nv_bfloat162 lo = __floats2bfloat162_rn(d * v.x, d * v.y);
        __nv_bfloat162 hi = __floats2bfloat162_rn(d * v.z, d * v.w);
        uint2 packed;
        packed.x = *reinterpret_cast<unsigned int*>(&lo);
        packed.y = *reinterpret_cast<unsigned int*>(&hi);
        ((uint2*)g_xb)[idx] = packed;
    }
    if (idx < e) {
        int s = ei[idx];
        int d = ei[e + idx];
        int pos = atomicAdd(&g_cursor[d], 1);
        g_col[pos] = s;
    }
}

// ---------------- agg1: t1_i = di*(sum xb'_s + xb'_i)  (warp per node) --------
// Cols fetched 16/batch by lanes (coalesced), broadcast via shfl.
__global__ void agg1_kernel(int n) {
    int warp = (blockIdx.x * blockDim.x + threadIdx.x) >> 5;
    int lane = threadIdx.x & 31;
    if (warp >= n) return;
    int i = warp;
    const char* xb = (const char*)g_xb + lane * 4;
    int p0 = g_rowptr[i], p1 = g_rowptr[i + 1];
    float2 acc = make_float2(0.f, 0.f);
    int p = p0;
    while (p1 - p >= 16) {
        int myc = g_col[p + (lane & 15)];
#pragma unroll
        for (int j = 0; j < 16; j++) {
            unsigned o = (unsigned)__shfl_sync(0xffffffffu, myc, j) << 7;
            float2 v = __bfloat1622float2(*(const __nv_bfloat162*)(xb + o));
            acc.x += v.x; acc.y += v.y;
        }
        p += 16;
    }
    int rem = p1 - p;
    if (rem > 0) {
        int myc = g_col[p + (lane < rem ? lane : 0)];
        for (int j = 0; j < rem; j++) {
            unsigned o = (unsigned)__shfl_sync(0xffffffffu, myc, j) << 7;
            float2 v = __bfloat1622float2(*(const __nv_bfloat162*)(xb + o));
            acc.x += v.x; acc.y += v.y;
        }
    }
    float di = g_dinv[i];
    float2 xi = __bfloat1622float2(*(const __nv_bfloat162*)(xb + ((unsigned)i << 7)));
    float2 r;
    r.x = di * (acc.x + xi.x);
    r.y = di * (acc.y + xi.y);
    *(float2*)(g_t1 + (size_t)i * 64 + lane * 2) = r;
}

// -------- GEMM1: h = elu(t1 @ W1 + b1); store hb' = bf16(dinv*h) --------------
__global__ void __launch_bounds__(256) gemm1_kernel(const float* __restrict__ W1,
                                                    const float* __restrict__ b1,
                                                    int n) {
    __shared__ float As[64 * 64];
    __shared__ float Ws[64 * 128];
    int tid = threadIdx.x;
    int base = blockIdx.x * 64;

    const float4* Wv = (const float4*)W1;
    float4* Wsv = (float4*)Ws;
#pragma unroll
    for (int i = 0; i < 8; i++) Wsv[tid + i * 256] = Wv[tid + i * 256];

    const float4* Av = (const float4*)(g_t1 + (size_t)base * 64);
    float4* Asv = (float4*)As;
#pragma unroll
    for (int i = 0; i < 4; i++) {
        int idx = tid + i * 256;
        int row = base + (idx >> 4);
        float4 v = (row < n) ? Av[idx] : make_float4(0.f, 0.f, 0.f, 0.f);
        Asv[idx] = v;
    }
    __syncthreads();

    int tx = tid & 31, ty = tid >> 5;
    int c0 = tx * 4, r0 = ty * 8;
    unsigned long long accp[8][2];
#pragma unroll
    for (int r = 0; r < 8; r++) { accp[r][0] = 0ull; accp[r][1] = 0ull; }

#pragma unroll 4
    for (int k = 0; k < 64; k++) {
        ulonglong2 bb = *(const ulonglong2*)(Ws + k * 128 + c0);
#pragma unroll
        for (int r = 0; r < 8; r++) {
            unsigned int au = __float_as_uint(As[(r0 + r) * 64 + k]);
            unsigned long long ap;
            asm("mov.b64 %0, {%1, %1};" : "=l"(ap) : "r"(au));
            asm("fma.rn.f32x2 %0, %1, %2, %0;" : "+l"(accp[r][0]) : "l"(ap), "l"(bb.x));
            asm("fma.rn.f32x2 %0, %1, %2, %0;" : "+l"(accp[r][1]) : "l"(ap), "l"(bb.y));
        }
    }

    float4 bias = *(const float4*)&b1[c0];
#pragma unroll
    for (int r = 0; r < 8; r++) {
        int row = base + r0 + r;
        if (row < n) {
            float di = g_dinv[row];
            unsigned int u0, u1, u2, u3;
            asm("mov.b64 {%0, %1}, %2;" : "=r"(u0), "=r"(u1) : "l"(accp[r][0]));
            asm("mov.b64 {%0, %1}, %2;" : "=r"(u2), "=r"(u3) : "l"(accp[r][1]));
            float4 o;
            o.x = __uint_as_float(u0) + bias.x;
            o.y = __uint_as_float(u1) + bias.y;
            o.z = __uint_as_float(u2) + bias.z;
            o.w = __uint_as_float(u3) + bias.w;
            o.x = (o.x > 0.f) ? o.x : expm1f(o.x);
            o.y = (o.y > 0.f) ? o.y : expm1f(o.y);
            o.z = (o.z > 0.f) ? o.z : expm1f(o.z);
            o.w = (o.w > 0.f) ? o.w : expm1f(o.w);
            __nv_bfloat162 lo = __floats2bfloat162_rn(di * o.x, di * o.y);
            __nv_bfloat162 hi = __floats2bfloat162_rn(di * o.z, di * o.w);
            uint2 packed;
            packed.x = *reinterpret_cast<unsigned int*>(&lo);
            packed.y = *reinterpret_cast<unsigned int*>(&hi);
            *(uint2*)(g_hb + (size_t)row * 128 + c0) = packed;
        }
    }
}

// -------- agg2 + mean-pool: shfl cols, pooled[g] += di*(sum hb'_s + hb'_i) ----
__device__ __forceinline__ float4 ld_h4o(const char* base, unsigned off) {
    uint2 raw = *(const uint2*)(base + off);
    __nv_bfloat162 b0 = *reinterpret_cast<__nv_bfloat162*>(&raw.x);
    __nv_bfloat162 b1 = *reinterpret_cast<__nv_bfloat162*>(&raw.y);
    float2 f0 = __bfloat1622float2(b0);
    float2 f1 = __bfloat1622float2(b1);
    return make_float4(f0.x, f0.y, f1.x, f1.y);
}

__global__ void __launch_bounds__(256) agg2_pool_kernel(const int* __restrict__ batch, int n) {
    __shared__ float ps[128];
    __shared__ int g0_s;
    int tid = threadIdx.x;
    int lane = tid & 31;
    int wid = tid >> 5;
    int node0 = blockIdx.x * 8;
    if (tid < 128) ps[tid] = 0.0f;
    if (tid == 0) g0_s = batch[node0 < n ? node0 : (n - 1)];
    __syncthreads();
    int g0 = g0_s;

    int i = node0 + wid;
    if (i < n) {
        const char* hb = (const char*)g_hb + lane * 8;
        int p0 = g_rowptr[i], p1 = g_rowptr[i + 1];
        float4 acc = make_float4(0.f, 0.f, 0.f, 0.f);
        int p = p0;
        while (p1 - p >= 16) {
            int myc = g_col[p + (lane & 15)];
#pragma unroll
            for (int j = 0; j < 16; j++) {
                unsigned o = (unsigned)__shfl_sync(0xffffffffu, myc, j) << 8;
                float4 v = ld_h4o(hb, o);
                acc.x += v.x; acc.y += v.y; acc.z += v.z; acc.w += v.w;
            }
            p += 16;
        }
        int rem = p1 - p;
        if (rem > 0) {
            int myc = g_col[p + (lane < rem ? lane : 0)];
            for (int j = 0; j < rem; j++) {
                unsigned o = (unsigned)__shfl_sync(0xffffffffu, myc, j) << 8;
                float4 v = ld_h4o(hb, o);
                acc.x += v.x; acc.y += v.y; acc.z += v.z; acc.w += v.w;
            }
        }
        float di = g_dinv[i];
        float4 hi = ld_h4o(hb, (unsigned)i << 8);
        float4 r;
        r.x = di * (acc.x + hi.x);
        r.y = di * (acc.y + hi.y);
        r.z = di * (acc.z + hi.z);
        r.w = di * (acc.w + hi.w);
        int g = batch[i];
        if (g == g0) {
            atomicAdd(&ps[lane * 4 + 0], r.x);
            atomicAdd(&ps[lane * 4 + 1], r.y);
            atomicAdd(&ps[lane * 4 + 2], r.z);
            atomicAdd(&ps[lane * 4 + 3], r.w);
        } else {
            float* pg = g_pooled + g * 128 + lane * 4;
            atomicAdd(pg + 0, r.x);
            atomicAdd(pg + 1, r.y);
            atomicAdd(pg + 2, r.z);
            atomicAdd(pg + 3, r.w);
        }
    }
    __syncthreads();
    if (tid < 128) atomicAdd(&g_pooled[g0 * 128 + tid], ps[tid]);
}

// ---------------- epilogue: W2 + MLP + log_softmax (1 block per graph) --------
__global__ void __launch_bounds__(128) final_kernel(
    const float* __restrict__ stats,
    const float* __restrict__ W2, const float* __restrict__ b2,
    const float* __restrict__ Wf1, const float* __restrict__ bf1,
    const float* __restrict__ Wf2, const float* __restrict__ bf2,
    float* __restrict__ out) {
    __shared__ float pm[128];
    __shared__ float zin[138];
    __shared__ float z1[20];
    __shared__ float z2[5];
    int g = blockIdx.x, t = threadIdx.x;
    float c = fmaxf((float)g_cnti[g], 1.0f);
    pm[t] = g_pooled[g * 128 + t] / c;
    __syncthreads();
    float acc = b2[t];
#pragma unroll 8
    for (int k = 0; k < 128; k++) acc = fmaf(pm[k], W2[k * 128 + t], acc);
    zin[t] = acc;
    if (t < 10) zin[128 + t] = stats[g * 10 + t];
    __syncthreads();
    if (t < 20) {
        float a = bf1[t];
        for (int k = 0; k < 138; k++) a = fmaf(zin[k], Wf1[k * 20 + t], a);
        z1[t] = fmaxf(a, 0.0f);
    }
    __syncthreads();
    if (t < 5) {
        float a = bf2[t];
        for (int k = 0; k < 20; k++) a = fmaf(z1[k], Wf2[k * 5 + t], a);
        z2[t] = a;
    }
    __syncthreads();
    if (t == 0) {
        float m = z2[0];
        for (int i = 1; i < 5; i++) m = fmaxf(m, z2[i]);
        float sum = 0.0f;
        for (int i = 0; i < 5; i++) sum += expf(z2[i] - m);
        float ls = m + logf(sum);
        for (int i = 0; i < 5; i++) out[g * 5 + i] = z2[i] - ls;
    }
}

// ---------------------------------------------------------------------------
extern "C" void kernel_launch(void* const* d_in, const int* in_sizes, int n_in,
                              void* d_out, int out_size) {
    const float* x     = (const float*)d_in[0];
    const int*   ei    = (const int*)d_in[1];
    const int*   batch = (const int*)d_in[2];
    const float* stats = (const float*)d_in[4];
    const float* W1    = (const float*)d_in[5];
    const float* b1    = (const float*)d_in[6];
    const float* W2    = (const float*)d_in[7];
    const float* b2    = (const float*)d_in[8];
    const float* Wf1   = (const float*)d_in[9];
    const float* bf1   = (const float*)d_in[10];
    const float* Wf2   = (const float*)d_in[11];
    const float* bf2   = (const float*)d_in[12];

    int n = in_sizes[0] / 64;
    int e = in_sizes[1] / 2;
    int G = in_sizes[4] / 10;
    int nb = (n + 4095) / 4096;
    int nconv = n * 16;
    int big = (nconv > e) ? nconv : e;

    init_kernel<<<(n + 255) / 256, 256>>>(n, G);
    count_kernel<<<(e + 255) / 256, 256>>>(ei, e);
    scan1_kernel<<<nb, 256>>>(n);
    scan2_kernel<<<1, 32>>>(nb, n);
    scan3_kernel<<<(n + 255) / 256, 256>>>(batch, n);
    convscatter_kernel<<<(big + 255) / 256, 256>>>(x, ei, nconv, e);
    agg1_kernel<<<(n * 32 + 255) / 256, 256>>>(n);
    gemm1_kernel<<<(n + 63) / 64, 256>>>(W1, b1, n);
    agg2_pool_kernel<<<(n + 7) / 8, 256>>>(batch, n);
    final_kernel<<<G, 128>>>(stats, W2, b2, Wf1, bf1, Wf2, bf2, (float*)d_out);
}

// round 13
// speedup vs baseline: 1.1068x; 1.0148x over previous
#include <cuda_runtime.h>
#include <cuda_bf16.h>
#include <math.h>

// ---------------------------------------------------------------------------
// GCN forward, 8 launches (self-cleaning graph replay):
//   count -> scan1(+fused scan2) -> scan3 -> convscatter -> agg1 -> gemm1
//   -> agg2+pool -> final
// g_indeg zeroed by gemm1 tail; g_pooled/g_cnti zeroed by final tail
// (graph replays identical sequence; static init covers run #1).
// bf16 dinv-prescaled payloads; fp32 accumulation; shfl-distributed cols.
// ---------------------------------------------------------------------------

#define MAXN 100000
#define MAXE 1600000
#define MAXG 64
#define MAXB ((MAXN + 4095) / 4096)

__device__ int   g_indeg[MAXN];
__device__ int   g_rowptr[MAXN + 1];
__device__ int   g_cursor[MAXN];
__device__ int   g_col[MAXE];
__device__ int   g_bsum[MAXB + 1];
__device__ int   g_cnti[MAXG];
__device__ float g_dinv[MAXN];
__device__ unsigned g_scan_done = 0;
__device__ __align__(16) __nv_bfloat16 g_xb[(size_t)MAXN * 64];
__device__ __align__(16) __nv_bfloat16 g_hb[(size_t)MAXN * 128];
__device__ __align__(16) float g_t1[(size_t)MAXN * 64];
__device__ float g_pooled[MAXG * 128];

// ---------------- count in-degree (indeg pre-zeroed by previous replay) ------
__global__ void count_kernel(const int* __restrict__ ei, int e) {
    int idx = blockIdx.x * blockDim.x + threadIdx.x;
    if (idx < e) atomicAdd(&g_indeg[ei[e + idx]], 1);
}

// ---------------- scan phase 1 + fused phase 2 (last-block pattern) ----------
__global__ void __launch_bounds__(256) scan1_kernel(int n) {
    __shared__ int sh[4096];
    __shared__ int wsum[8];
    __shared__ bool is_last;
    int t = threadIdx.x;
    int base = blockIdx.x * 4096;
#pragma unroll
    for (int j = 0; j < 16; j++) {
        int idx = base + t + j * 256;
        sh[t + j * 256] = (idx < n) ? g_indeg[idx] : 0;
    }
    __syncthreads();
    int v[16];
    int run = 0;
#pragma unroll
    for (int j = 0; j < 16; j++) { v[j] = run; run += sh[t * 16 + j]; }
    int lane = t & 31, w = t >> 5;
    int incl = run;
#pragma unroll
    for (int off = 1; off < 32; off <<= 1) {
        int tmp = __shfl_up_sync(0xffffffffu, incl, off);
        if (lane >= off) incl += tmp;
    }
    if (lane == 31) wsum[w] = incl;
    __syncthreads();
    if (t == 0) {
        int s = 0;
#pragma unroll
        for (int k = 0; k < 8; k++) { int x2 = wsum[k]; wsum[k] = s; s += x2; }
        g_bsum[blockIdx.x] = s;
    }
    __syncthreads();
    int texcl = wsum[w] + incl - run;
#pragma unroll
    for (int j = 0; j < 16; j++) sh[t * 16 + j] = texcl + v[j];
    __syncthreads();
#pragma unroll
    for (int j = 0; j < 16; j++) {
        int idx = base + t + j * 256;
        if (idx < n) g_rowptr[idx] = sh[t + j * 256];
    }
    // fused scan2: last block to finish scans the block sums (nb <= 32)
    __threadfence();
    if (t == 0) {
        unsigned ticket = atomicAdd(&g_scan_done, 1u);
        is_last = (ticket == gridDim.x - 1);
    }
    __syncthreads();
    if (is_last) {
        if (t < 32) {
            int nb = gridDim.x;
            int x = (t < nb) ? g_bsum[t] : 0;
            int incl2 = x;
#pragma unroll
            for (int off = 1; off < 32; off <<= 1) {
                int tmp = __shfl_up_sync(0xffffffffu, incl2, off);
                if (t >= off) incl2 += tmp;
            }
            if (t < nb) g_bsum[t] = incl2 - x;
            int total = __shfl_sync(0xffffffffu, incl2, 31);
            if (t == 0) {
                g_rowptr[n] = total;
                g_scan_done = 0;
            }
        }
    }
}

// -------- scan phase 3: offsets + dinv + cursor + graph counts -----------------
__global__ void scan3_kernel(const int* __restrict__ batch, int n) {
    int i = blockIdx.x * blockDim.x + threadIdx.x;
    if (i < n) {
        int r = g_rowptr[i] + g_bsum[i >> 12];
        g_rowptr[i] = r;
        g_cursor[i] = r;
        g_dinv[i] = rsqrtf((float)(g_indeg[i] + 1));
        atomicAdd(&g_cnti[batch[i]], 1);
    }
}

// -------- convert xb' = bf16(dinv*x) + scatter edges (merged) ------------------
__global__ void convscatter_kernel(const float* __restrict__ x,
                                   const int* __restrict__ ei,
                                   int nconv, int e) {
    int idx = blockIdx.x * blockDim.x + threadIdx.x;
    if (idx < nconv) {
        float d = g_dinv[idx >> 4];
        float4 v = ((const float4*)x)[idx];
        __nv_bfloat162 lo = __floats2bfloat162_rn(d * v.x, d * v.y);
        __nv_bfloat162 hi = __floats2bfloat162_rn(d * v.z, d * v.w);
        uint2 packed;
        packed.x = *reinterpret_cast<unsigned int*>(&lo);
        packed.y = *reinterpret_cast<unsigned int*>(&hi);
        ((uint2*)g_xb)[idx] = packed;
    }
    if (idx < e) {
        int s = ei[idx];
        int d = ei[e + idx];
        int pos = atomicAdd(&g_cursor[d], 1);
        g_col[pos] = s;
    }
}

// ---------------- agg1: t1_i = di*(sum xb'_s + xb'_i)  (warp per node) --------
__global__ void agg1_kernel(int n) {
    int warp = (blockIdx.x * blockDim.x + threadIdx.x) >> 5;
    int lane = threadIdx.x & 31;
    if (warp >= n) return;
    int i = warp;
    const char* xb = (const char*)g_xb + lane * 4;
    int p0 = g_rowptr[i], p1 = g_rowptr[i + 1];
    float2 acc = make_float2(0.f, 0.f);
    int p = p0;
    while (p1 - p >= 16) {
        int myc = g_col[p + (lane & 15)];
#pragma unroll
        for (int j = 0; j < 16; j++) {
            unsigned o = (unsigned)__shfl_sync(0xffffffffu, myc, j) << 7;
            float2 v = __bfloat1622float2(*(const __nv_bfloat162*)(xb + o));
            acc.x += v.x; acc.y += v.y;
        }
        p += 16;
    }
    int rem = p1 - p;
    if (rem > 0) {
        int myc = g_col[p + (lane < rem ? lane : 0)];
        for (int j = 0; j < rem; j++) {
            unsigned o = (unsigned)__shfl_sync(0xffffffffu, myc, j) << 7;
            float2 v = __bfloat1622float2(*(const __nv_bfloat162*)(xb + o));
            acc.x += v.x; acc.y += v.y;
        }
    }
    float di = g_dinv[i];
    float2 xi = __bfloat1622float2(*(const __nv_bfloat162*)(xb + ((unsigned)i << 7)));
    float2 r;
    r.x = di * (acc.x + xi.x);
    r.y = di * (acc.y + xi.y);
    *(float2*)(g_t1 + (size_t)i * 64 + lane * 2) = r;
}

// -------- GEMM1: h = elu(t1 @ W1 + b1); hb' = bf16(dinv*h); zero indeg --------
__global__ void __launch_bounds__(256) gemm1_kernel(const float* __restrict__ W1,
                                                    const float* __restrict__ b1,
                                                    int n) {
    __shared__ float As[64 * 64];
    __shared__ float Ws[64 * 128];
    int tid = threadIdx.x;
    int base = blockIdx.x * 64;

    // self-clean for next graph replay: zero g_indeg (dead after scan3)
    int gid = blockIdx.x * 256 + tid;
    if (gid < n) g_indeg[gid] = 0;

    const float4* Wv = (const float4*)W1;
    float4* Wsv = (float4*)Ws;
#pragma unroll
    for (int i = 0; i < 8; i++) Wsv[tid + i * 256] = Wv[tid + i * 256];

    const float4* Av = (const float4*)(g_t1 + (size_t)base * 64);
    float4* Asv = (float4*)As;
#pragma unroll
    for (int i = 0; i < 4; i++) {
        int idx = tid + i * 256;
        int row = base + (idx >> 4);
        float4 v = (row < n) ? Av[idx] : make_float4(0.f, 0.f, 0.f, 0.f);
        Asv[idx] = v;
    }
    __syncthreads();

    int tx = tid & 31, ty = tid >> 5;
    int c0 = tx * 4, r0 = ty * 8;
    unsigned long long accp[8][2];
#pragma unroll
    for (int r = 0; r < 8; r++) { accp[r][0] = 0ull; accp[r][1] = 0ull; }

#pragma unroll 4
    for (int k = 0; k < 64; k++) {
        ulonglong2 bb = *(const ulonglong2*)(Ws + k * 128 + c0);
#pragma unroll
        for (int r = 0; r < 8; r++) {
            unsigned int au = __float_as_uint(As[(r0 + r) * 64 + k]);
            unsigned long long ap;
            asm("mov.b64 %0, {%1, %1};" : "=l"(ap) : "r"(au));
            asm("fma.rn.f32x2 %0, %1, %2, %0;" : "+l"(accp[r][0]) : "l"(ap), "l"(bb.x));
            asm("fma.rn.f32x2 %0, %1, %2, %0;" : "+l"(accp[r][1]) : "l"(ap), "l"(bb.y));
        }
    }

    float4 bias = *(const float4*)&b1[c0];
#pragma unroll
    for (int r = 0; r < 8; r++) {
        int row = base + r0 + r;
        if (row < n) {
            float di = g_dinv[row];
            unsigned int u0, u1, u2, u3;
            asm("mov.b64 {%0, %1}, %2;" : "=r"(u0), "=r"(u1) : "l"(accp[r][0]));
            asm("mov.b64 {%0, %1}, %2;" : "=r"(u2), "=r"(u3) : "l"(accp[r][1]));
            float4 o;
            o.x = __uint_as_float(u0) + bias.x;
            o.y = __uint_as_float(u1) + bias.y;
            o.z = __uint_as_float(u2) + bias.z;
            o.w = __uint_as_float(u3) + bias.w;
            o.x = (o.x > 0.f) ? o.x : expm1f(o.x);
            o.y = (o.y > 0.f) ? o.y : expm1f(o.y);
            o.z = (o.z > 0.f) ? o.z : expm1f(o.z);
            o.w = (o.w > 0.f) ? o.w : expm1f(o.w);
            __nv_bfloat162 lo = __floats2bfloat162_rn(di * o.x, di * o.y);
            __nv_bfloat162 hi = __floats2bfloat162_rn(di * o.z, di * o.w);
            uint2 packed;
            packed.x = *reinterpret_cast<unsigned int*>(&lo);
            packed.y = *reinterpret_cast<unsigned int*>(&hi);
            *(uint2*)(g_hb + (size_t)row * 128 + c0) = packed;
        }
    }
}

// -------- agg2 + mean-pool: shfl cols, pooled[g] += di*(sum hb'_s + hb'_i) ----
__device__ __forceinline__ float4 ld_h4o(const char* base, unsigned off) {
    uint2 raw = *(const uint2*)(base + off);
    __nv_bfloat162 b0 = *reinterpret_cast<__nv_bfloat162*>(&raw.x);
    __nv_bfloat162 b1 = *reinterpret_cast<__nv_bfloat162*>(&raw.y);
    float2 f0 = __bfloat1622float2(b0);
    float2 f1 = __bfloat1622float2(b1);
    return make_float4(f0.x, f0.y, f1.x, f1.y);
}

__global__ void __launch_bounds__(256) agg2_pool_kernel(const int* __restrict__ batch, int n) {
    __shared__ float ps[128];
    __shared__ int g0_s;
    int tid = threadIdx.x;
    int lane = tid & 31;
    int wid = tid >> 5;
    int node0 = blockIdx.x * 8;
    if (tid < 128) ps[tid] = 0.0f;
    if (tid == 0) g0_s = batch[node0 < n ? node0 : (n - 1)];
    __syncthreads();
    int g0 = g0_s;

    int i = node0 + wid;
    if (i < n) {
        const char* hb = (const char*)g_hb + lane * 8;
        int p0 = g_rowptr[i], p1 = g_rowptr[i + 1];
        float4 acc = make_float4(0.f, 0.f, 0.f, 0.f);
        int p = p0;
        while (p1 - p >= 16) {
            int myc = g_col[p + (lane & 15)];
#pragma unroll
            for (int j = 0; j < 16; j++) {
                unsigned o = (unsigned)__shfl_sync(0xffffffffu, myc, j) << 8;
                float4 v = ld_h4o(hb, o);
                acc.x += v.x; acc.y += v.y; acc.z += v.z; acc.w += v.w;
            }
            p += 16;
        }
        int rem = p1 - p;
        if (rem > 0) {
            int myc = g_col[p + (lane < rem ? lane : 0)];
            for (int j = 0; j < rem; j++) {
                unsigned o = (unsigned)__shfl_sync(0xffffffffu, myc, j) << 8;
                float4 v = ld_h4o(hb, o);
                acc.x += v.x; acc.y += v.y; acc.z += v.z; acc.w += v.w;
            }
        }
        float di = g_dinv[i];
        float4 hi = ld_h4o(hb, (unsigned)i << 8);
        float4 r;
        r.x = di * (acc.x + hi.x);
        r.y = di * (acc.y + hi.y);
        r.z = di * (acc.z + hi.z);
        r.w = di * (acc.w + hi.w);
        int g = batch[i];
        if (g == g0) {
            atomicAdd(&ps[lane * 4 + 0], r.x);
            atomicAdd(&ps[lane * 4 + 1], r.y);
            atomicAdd(&ps[lane * 4 + 2], r.z);
            atomicAdd(&ps[lane * 4 + 3], r.w);
        } else {
            float* pg = g_pooled + g * 128 + lane * 4;
            atomicAdd(pg + 0, r.x);
            atomicAdd(pg + 1, r.y);
            atomicAdd(pg + 2, r.z);
            atomicAdd(pg + 3, r.w);
        }
    }
    __syncthreads();
    if (tid < 128) atomicAdd(&g_pooled[g0 * 128 + tid], ps[tid]);
}

// ------- epilogue: W2 + MLP + log_softmax; zero pooled/cnti for next replay ---
__global__ void __launch_bounds__(128) final_kernel(
    const float* __restrict__ stats,
    const float* __restrict__ W2, const float* __restrict__ b2,
    const float* __restrict__ Wf1, const float* __restrict__ bf1,
    const float* __restrict__ Wf2, const float* __restrict__ bf2,
    float* __restrict__ out) {
    __shared__ float pm[128];
    __shared__ float zin[138];
    __shared__ float z1[20];
    __shared__ float z2[5];
    int g = blockIdx.x, t = threadIdx.x;
    float c = fmaxf((float)g_cnti[g], 1.0f);
    pm[t] = g_pooled[g * 128 + t] / c;
    // self-clean for next graph replay
    g_pooled[g * 128 + t] = 0.0f;
    if (t == 0) g_cnti[g] = 0;
    __syncthreads();
    float acc = b2[t];
#pragma unroll 8
    for (int k = 0; k < 128; k++) acc = fmaf(pm[k], W2[k * 128 + t], acc);
    zin[t] = acc;
    if (t < 10) zin[128 + t] = stats[g * 10 + t];
    __syncthreads();
    if (t < 20) {
        float a = bf1[t];
        for (int k = 0; k < 138; k++) a = fmaf(zin[k], Wf1[k * 20 + t], a);
        z1[t] = fmaxf(a, 0.0f);
    }
    __syncthreads();
    if (t < 5) {
        float a = bf2[t];
        for (int k = 0; k < 20; k++) a = fmaf(z1[k], Wf2[k * 5 + t], a);
        z2[t] = a;
    }
    __syncthreads();
    if (t == 0) {
        float m = z2[0];
        for (int i = 1; i < 5; i++) m = fmaxf(m, z2[i]);
        float sum = 0.0f;
        for (int i = 0; i < 5; i++) sum += expf(z2[i] - m);
        float ls = m + logf(sum);
        for (int i = 0; i < 5; i++) out[g * 5 + i] = z2[i] - ls;
    }
}

// ---------------------------------------------------------------------------
extern "C" void kernel_launch(void* const* d_in, const int* in_sizes, int n_in,
                              void* d_out, int out_size) {
    const float* x     = (const float*)d_in[0];
    const int*   ei    = (const int*)d_in[1];
    const int*   batch = (const int*)d_in[2];
    const float* stats = (const float*)d_in[4];
    const float* W1    = (const float*)d_in[5];
    const float* b1    = (const float*)d_in[6];
    const float* W2    = (const float*)d_in[7];
    const float* b2    = (const float*)d_in[8];
    const float* Wf1   = (const float*)d_in[9];
    const float* bf1   = (const float*)d_in[10];
    const float* Wf2   = (const float*)d_in[11];
    const float* bf2   = (const float*)d_in[12];

    int n = in_sizes[0] / 64;
    int e = in_sizes[1] / 2;
    int G = in_sizes[4] / 10;
    int nb = (n + 4095) / 4096;
    int nconv = n * 16;
    int big = (nconv > e) ? nconv : e;

    count_kernel<<<(e + 255) / 256, 256>>>(ei, e);
    scan1_kernel<<<nb, 256>>>(n);
    scan3_kernel<<<(n + 255) / 256, 256>>>(batch, n);
    convscatter_kernel<<<(big + 255) / 256, 256>>>(x, ei, nconv, e);
    agg1_kernel<<<(n * 32 + 255) / 256, 256>>>(n);
    gemm1_kernel<<<(n + 63) / 64, 256>>>(W1, b1, n);
    agg2_pool_kernel<<<(n + 7) / 8, 256>>>(batch, n);
    final_kernel<<<G, 128>>>(stats, W2, b2, Wf1, bf1, Wf2, bf2, (float*)d_out);
}